// round 8
// baseline (speedup 1.0000x reference)
#include <cuda_runtime.h>
#include <cuda_fp16.h>

// Problem constants (fixed shapes from reference setup_inputs)
#define RR 4          // relations
#define NS 20000      // N_SRC
#define NV 20000      // N_VUL (= N)
#define DD 256        // feature dim
#define EE 640000     // edges per relation
#define KK 16         // candidates per node
#define RD (RR*DD)    // 1024 floats per node across relations
#define NTILE 20
#define TILESZ 1000   // NV / NTILE

// ---- scratch (static device globals; allocation-free per harness rules) ----
__device__ __half  g_x16[(size_t)RR*NS*DD];   // fp16 copy of x (41MB)
__device__ float2  g_pair[RR*EE];             // (w, src-as-int-bits) in CSR order (20MB)
__device__ int     g_cnt[RR*NV];              // in-degree histogram
__device__ int     g_offs[RR*(NV+1)];         // CSR offsets
__device__ int     g_cursor[RR*NV];           // scatter cursors
__device__ int     g_tilesum[RR*NTILE];       // per-tile degree sums
__device__ __half  g_H16[(size_t)NV*RD];      // H fp16 [n][r][d] (41MB)

// ---------------------------------------------------------------------------
__global__ void k_init() {
    int i = blockIdx.x * blockDim.x + threadIdx.x;
    if (i < RR*NV) g_cnt[i] = 0;
}

// x fp32 -> fp16 (each thread: 4 elements)
__global__ void k_convert(const float* __restrict__ x) {
    int i = blockIdx.x * blockDim.x + threadIdx.x;   // exactly RR*NS*DD/4 threads
    float4 v = __ldg(((const float4*)x) + i);
    __half2* o = (__half2*)g_x16;
    o[2*i]   = __floats2half2_rn(v.x, v.y);
    o[2*i+1] = __floats2half2_rn(v.z, v.w);
}

// Degree histogram (scalar)
__global__ void k_hist(const int* __restrict__ dst_idx) {
    int idx = blockIdx.x * blockDim.x + threadIdx.x;
    if (idx >= RR*EE) return;
    int r = idx / EE;
    atomicAdd(&g_cnt[r*NV + dst_idx[idx]], 1);
}

// Scan phase 1: per-tile sums. grid = RR*NTILE = 80 blocks of 256.
__global__ void __launch_bounds__(256) k_scan1() {
    __shared__ int wsum[8];
    int blk = blockIdx.x;
    int r = blk / NTILE, tile = blk % NTILE;
    int t = threadIdx.x;
    int base = r*NV + tile*TILESZ;
    int s = 0;
#pragma unroll
    for (int j = 0; j < 4; j++) {
        int i = t*4 + j;
        if (i < TILESZ) s += g_cnt[base + i];
    }
#pragma unroll
    for (int o = 16; o; o >>= 1) s += __shfl_down_sync(0xffffffffu, s, o);
    if ((t & 31) == 0) wsum[t >> 5] = s;
    __syncthreads();
    if (t < 8) {
        int v = wsum[t];
#pragma unroll
        for (int o = 4; o; o >>= 1) v += __shfl_down_sync(0xffu, v, o);
        if (t == 0) g_tilesum[blk] = v;
    }
}

// Scan phase 2: per-tile exclusive scan + tile prefix. grid = 80 blocks of 256.
__global__ void __launch_bounds__(256) k_scan2() {
    __shared__ int wpre[8];
    int blk = blockIdx.x;
    int r = blk / NTILE, tile = blk % NTILE;
    int t = threadIdx.x, lane = t & 31, w = t >> 5;
    int base = r*NV + tile*TILESZ;
    int v[4]; int s = 0;
#pragma unroll
    for (int j = 0; j < 4; j++) {
        int i = t*4 + j;
        v[j] = (i < TILESZ) ? g_cnt[base + i] : 0;
        s += v[j];
    }
    int sc = s;   // warp-inclusive scan of per-thread sums
#pragma unroll
    for (int o = 1; o < 32; o <<= 1) {
        int u = __shfl_up_sync(0xffffffffu, sc, o);
        if (lane >= o) sc += u;
    }
    if (lane == 31) wpre[w] = sc;
    __syncthreads();
    if (t == 0) { int run = 0; for (int i = 0; i < 8; i++) { int x = wpre[i]; wpre[i] = run; run += x; } }
    __syncthreads();
    int tilepre = 0;
    for (int i = 0; i < tile; i++) tilepre += g_tilesum[r*NTILE + i];
    int excl = tilepre + wpre[w] + sc - s;
#pragma unroll
    for (int j = 0; j < 4; j++) {
        int i = t*4 + j;
        if (i < TILESZ) {
            g_offs[r*(NV+1) + tile*TILESZ + i] = excl;
            g_cursor[base + i] = excl;
            excl += v[j];
        }
    }
    if (tile == NTILE-1 && t == 255) g_offs[r*(NV+1) + NV] = excl;  // grand total
}

// Combined: softmax weight (max-subtraction dropped: logits bounded in [-2,2])
// + counting-sort scatter of paired (w, src) into CSR order.
__global__ void k_scatter2(const float* __restrict__ d,
                           const float* __restrict__ d1,
                           const float* __restrict__ d2,
                           const int*   __restrict__ src_idx,
                           const int*   __restrict__ dst_idx,
                           const int*   __restrict__ psplit) {
    int idx = blockIdx.x * blockDim.x + threadIdx.x;
    if (idx >= RR*EE) return;
    int r   = idx / EE;
    int src = src_idx[idx];
    int dst = dst_idx[idx];
    float dd = __ldg(&d[r*NS + src]);
    int   split = *psplit;
    float lg = (dst < split) ? (__ldg(&d1[r*NS + src]) / dd)
                             : (-__ldg(&d2[r*NS + src]) / dd);
    float w = expf(lg);
    int pos = atomicAdd(&g_cursor[r*NV + dst], 1);
    g_pair[r*EE + pos] = make_float2(w, __int_as_float(src));
}

// fp16 octet FMA into fp32 accumulators
__device__ __forceinline__ void fma8(float* acc, float w, float4 raw) {
    float2 f0 = __half22float2(*(__half2*)&raw.x);
    float2 f1 = __half22float2(*(__half2*)&raw.y);
    float2 f2 = __half22float2(*(__half2*)&raw.z);
    float2 f3 = __half22float2(*(__half2*)&raw.w);
    acc[0] += w*f0.x; acc[1] += w*f0.y; acc[2] += w*f1.x; acc[3] += w*f1.y;
    acc[4] += w*f2.x; acc[5] += w*f2.y; acc[6] += w*f3.x; acc[7] += w*f3.y;
}

// Gather-aggregate: one block per node; 8 warps = 4 relations x 2 halves.
// Each warp runs the proven R3 loop body on HALF of its (rel,node) edge list
// (halves the per-warp serial latency chain); fp32 partials combined in smem.
// wsum is warp-uniform (weights broadcast), so the combine is one scalar.
__global__ void __launch_bounds__(256) k_aggregate() {
    __shared__ float s_acc[RR][DD];   // 4KB partial sums from half 0
    __shared__ float s_w[RR];
    int n    = blockIdx.x;
    int w    = threadIdx.x >> 5;     // 0..7
    int r    = w >> 1;
    int half = w & 1;
    int lane = threadIdx.x & 31;
    int beg = g_offs[r*(NV+1) + n];
    int end = g_offs[r*(NV+1) + n + 1];
    int len = end - beg;
    int mid = beg + ((len + 1) >> 1);
    int b0 = half ? mid : beg;
    int e0 = half ? end : mid;
    const float4* __restrict__ xr = (const float4*)(g_x16 + (size_t)r * NS * DD); // 32 float4/row
    const float2* __restrict__ pr = g_pair + (size_t)r * EE;

    float acc[8] = {0,0,0,0,0,0,0,0};
    float wsum = 0.f;
    int i = b0;
    for (; i + 8 <= e0; i += 8) {
        float2 p[8];
        float4 v[8];
#pragma unroll
        for (int j = 0; j < 8; j++) p[j] = __ldg(pr + i + j);
#pragma unroll
        for (int j = 0; j < 8; j++)
            v[j] = __ldg(xr + (size_t)__float_as_int(p[j].y)*32 + lane);
#pragma unroll
        for (int j = 0; j < 8; j++) { fma8(acc, p[j].x, v[j]); wsum += p[j].x; }
    }
    for (; i < e0; i++) {
        float2 p = __ldg(pr + i);
        float4 v = __ldg(xr + (size_t)__float_as_int(p.y)*32 + lane);
        fma8(acc, p.x, v);
        wsum += p.x;
    }

    if (half == 0) {
#pragma unroll
        for (int j = 0; j < 8; j++) s_acc[r][lane*8 + j] = acc[j];
        if (lane == 0) s_w[r] = wsum;
    }
    __syncthreads();
    if (half == 1) {
#pragma unroll
        for (int j = 0; j < 8; j++) acc[j] += s_acc[r][lane*8 + j];
        wsum += s_w[r];
        float inv = 1.f / fmaxf(wsum, 1e-9f);
        float4 hv;
        *(__half2*)&hv.x = __floats2half2_rn(acc[0]*inv, acc[1]*inv);
        *(__half2*)&hv.y = __floats2half2_rn(acc[2]*inv, acc[3]*inv);
        *(__half2*)&hv.z = __floats2half2_rn(acc[4]*inv, acc[5]*inv);
        *(__half2*)&hv.w = __floats2half2_rn(acc[6]*inv, acc[7]*inv);
        *(float4*)(g_H16 + (size_t)n * RD + r * DD + lane * 8) = hv;
    }
}

// Candidate mask + relation-sum (round-3 verbatim). One block per node, 256 thr.
__global__ void __launch_bounds__(256) k_mask(const int* __restrict__ cand,
                                              float* __restrict__ out) {
    __shared__ float buf[RD];
    __shared__ float s_sq[KK];
    int n = blockIdx.x;
    int t = threadIdx.x;
    int lane = t & 31;

    const uint2* __restrict__ Hh = (const uint2*)g_H16;   // 8B = 4 halves; RD/4 per row
    uint2 hr = __ldg(&Hh[(size_t)n * (RD/4) + t]);
    float2 h01 = __half22float2(*(__half2*)&hr.x);
    float2 h23 = __half22float2(*(__half2*)&hr.y);
    float4 h4 = make_float4(h01.x, h01.y, h23.x, h23.y);

    if (t < KK) s_sq[t] = 0.f;
    __syncthreads();

    float4 df[KK];
#pragma unroll
    for (int k = 0; k < KK; k++) {
        int c = __ldg(&cand[n*KK + k]);
        uint2 cr = __ldg(&Hh[(size_t)c * (RD/4) + t]);
        float2 f01 = __half22float2(*(__half2*)&cr.x);
        float2 f23 = __half22float2(*(__half2*)&cr.y);
        float4 d4;
        d4.x = h4.x - f01.x; d4.y = h4.y - f01.y;
        d4.z = h4.z - f23.x; d4.w = h4.w - f23.y;
        df[k] = d4;
        float p = d4.x*d4.x + d4.y*d4.y + d4.z*d4.z + d4.w*d4.w;
#pragma unroll
        for (int o = 16; o; o >>= 1) p += __shfl_down_sync(0xffffffffu, p, o);
        if (lane == 0) atomicAdd(&s_sq[k], p);
    }
    __syncthreads();

    float lg[KK];
    float mx = -1e30f;
#pragma unroll
    for (int k = 0; k < KK; k++) { lg[k] = -sqrtf(s_sq[k]); mx = fmaxf(mx, lg[k]); }
    float den = 0.f;
    float ek[KK];
#pragma unroll
    for (int k = 0; k < KK; k++) { ek[k] = expf(lg[k] - mx); den += ek[k]; }
    float invden = 1.f / den;

    float4 acc = make_float4(0.f, 0.f, 0.f, 0.f);
#pragma unroll
    for (int k = 0; k < KK; k++) {
        float a = ek[k] * invden;
        acc.x += a * df[k].x * df[k].x;
        acc.y += a * df[k].y * df[k].y;
        acc.z += a * df[k].z * df[k].z;
        acc.w += a * df[k].w * df[k].w;
    }
    float4 mv;
    mv.x = h4.x * expf(-acc.x);
    mv.y = h4.y * expf(-acc.y);
    mv.z = h4.z * expf(-acc.z);
    mv.w = h4.w * expf(-acc.w);
    ((float4*)buf)[t] = mv;
    __syncthreads();

    out[(size_t)n * DD + t] = buf[t] + buf[DD + t] + buf[2*DD + t] + buf[3*DD + t];
}

// ---------------------------------------------------------------------------
extern "C" void kernel_launch(void* const* d_in, const int* in_sizes, int n_in,
                              void* d_out, int out_size) {
    const float* x    = (const float*)d_in[0];   // [R, NS, D]
    const float* d    = (const float*)d_in[1];   // [R, NS]
    const float* d1   = (const float*)d_in[2];   // [R, NS]
    const float* d2   = (const float*)d_in[3];   // [R, NS]
    const int*   src  = (const int*)d_in[4];     // [R, E]
    const int*   dst  = (const int*)d_in[5];     // [R, E]
    const int*   cand = (const int*)d_in[6];     // [NV, K]
    const int*   spl  = (const int*)d_in[7];     // scalar splitvulid
    float* out = (float*)d_out;                  // [NV, D]

    k_init<<<(RR*NV + 255)/256, 256>>>();
    k_convert<<<(RR*NS*DD/4 + 255)/256, 256>>>(x);
    k_hist<<<(RR*EE + 255)/256, 256>>>(dst);
    k_scan1<<<RR*NTILE, 256>>>();
    k_scan2<<<RR*NTILE, 256>>>();
    k_scatter2<<<(RR*EE + 255)/256, 256>>>(d, d1, d2, src, dst, spl);
    k_aggregate<<<NV, 256>>>();
    k_mask<<<NV, 256>>>(cand, out);
}

// round 12
// speedup vs baseline: 1.0533x; 1.0533x over previous
#include <cuda_runtime.h>
#include <cuda_fp16.h>

// Problem constants (fixed shapes from reference setup_inputs)
#define RR 4          // relations
#define NS 20000      // N_SRC
#define NV 20000      // N_VUL (= N)
#define DD 256        // feature dim
#define EE 640000     // edges per relation
#define KK 16         // candidates per node
#define RD (RR*DD)    // 1024 floats per node across relations

// ---- scratch (static device globals; allocation-free per harness rules) ----
__device__ __half  g_x16[(size_t)RR*NS*DD];   // fp16 copy of x (41MB)
__device__ float2  g_pair[RR*EE];             // (w, src-as-int-bits) in CSR order (20MB)
__device__ int     g_cnt[RR*NV];              // in-degree histogram (zeroed by k_scan after use)
__device__ int     g_offs[RR*(NV+1)];         // CSR offsets
__device__ int     g_cursor[RR*NV];           // scatter cursors
__device__ __half  g_H16[(size_t)NV*RD];      // H fp16 [n][r][d] (41MB)

// ---------------------------------------------------------------------------
// Fused: degree histogram (1 edge/thread) + x fp32->fp16 convert.
// RR*NS*DD = 20.48M floats = 10.24M half2 = 4 * (RR*EE) half2, so each of the
// RR*EE threads converts 4 half2 at stride RR*EE (fully coalesced passes).
__global__ void k_conv_hist(const float* __restrict__ x,
                            const int*   __restrict__ dst_idx) {
    int idx = blockIdx.x * blockDim.x + threadIdx.x;
    if (idx >= RR*EE) return;
    const float2* __restrict__ x2 = (const float2*)x;
    __half2* __restrict__ o = (__half2*)g_x16;
#pragma unroll
    for (int j = 0; j < 4; j++) {
        int e = idx + j * (RR*EE);
        float2 v = __ldg(x2 + e);
        o[e] = __floats2half2_rn(v.x, v.y);
    }
    // histogram one edge
    int r = idx / EE;
    atomicAdd(&g_cnt[r*NV + dst_idx[idx]], 1);
}

// Coalesced tiled exclusive scan. One block of 1024 per relation.
// Also re-zeroes g_cnt after reading (replaces k_init for graph replays;
// first execution relies on static zero-initialization of device globals).
__global__ void __launch_bounds__(1024) k_scan() {
    __shared__ int warpsums[32];
    int r    = blockIdx.x;
    int t    = threadIdx.x;
    int lane = t & 31;
    int w    = t >> 5;
    int carry = 0;
    const int NT = (NV + 1023) / 1024;   // 20 tiles
    for (int tile = 0; tile < NT; tile++) {
        int i = tile * 1024 + t;
        int v = (i < NV) ? g_cnt[r*NV + i] : 0;
        int s = v;
#pragma unroll
        for (int o = 1; o < 32; o <<= 1) {
            int u = __shfl_up_sync(0xffffffffu, s, o);
            if (lane >= o) s += u;
        }
        if (lane == 31) warpsums[w] = s;
        __syncthreads();
        if (w == 0) {
            int ws = warpsums[lane];
#pragma unroll
            for (int o = 1; o < 32; o <<= 1) {
                int u = __shfl_up_sync(0xffffffffu, ws, o);
                if (lane >= o) ws += u;
            }
            warpsums[lane] = ws;
        }
        __syncthreads();
        int excl = carry + ((w > 0) ? warpsums[w-1] : 0) + s - v;
        if (i < NV) {
            g_offs[r*(NV+1) + i] = excl;
            g_cursor[r*NV + i]   = excl;
            g_cnt[r*NV + i]      = 0;     // reset for next graph replay
        }
        carry += warpsums[31];
        __syncthreads();
    }
    if (t == 0) g_offs[r*(NV+1) + NV] = carry;
}

// Combined: softmax weight (max-subtraction dropped: logits bounded in [-2,2])
// + counting-sort scatter of paired (w, src) into CSR order.
__global__ void k_scatter2(const float* __restrict__ d,
                           const float* __restrict__ d1,
                           const float* __restrict__ d2,
                           const int*   __restrict__ src_idx,
                           const int*   __restrict__ dst_idx,
                           const int*   __restrict__ psplit) {
    int idx = blockIdx.x * blockDim.x + threadIdx.x;
    if (idx >= RR*EE) return;
    int r   = idx / EE;
    int src = src_idx[idx];
    int dst = dst_idx[idx];
    float dd = __ldg(&d[r*NS + src]);
    int   split = *psplit;
    float lg = (dst < split) ? (__ldg(&d1[r*NS + src]) / dd)
                             : (-__ldg(&d2[r*NS + src]) / dd);
    float w = expf(lg);
    int pos = atomicAdd(&g_cursor[r*NV + dst], 1);
    g_pair[r*EE + pos] = make_float2(w, __int_as_float(src));
}

// fp16 octet FMA into fp32 accumulators
__device__ __forceinline__ void fma8(float* acc, float w, float4 raw) {
    float2 f0 = __half22float2(*(__half2*)&raw.x);
    float2 f1 = __half22float2(*(__half2*)&raw.y);
    float2 f2 = __half22float2(*(__half2*)&raw.z);
    float2 f3 = __half22float2(*(__half2*)&raw.w);
    acc[0] += w*f0.x; acc[1] += w*f0.y; acc[2] += w*f1.x; acc[3] += w*f1.y;
    acc[4] += w*f2.x; acc[5] += w*f2.y; acc[6] += w*f3.x; acc[7] += w*f3.y;
}

// Gather-aggregate (R6/541us winner, VERBATIM): one block per node, warp r
// handles relation r. Lane owns 8 consecutive halves (one 16B load per edge).
// 4th launch -> captured by ncu this round.
__global__ void __launch_bounds__(128) k_aggregate() {
    int n    = blockIdx.x;
    int r    = threadIdx.x >> 5;
    int lane = threadIdx.x & 31;
    int beg = g_offs[r*(NV+1) + n];
    int end = g_offs[r*(NV+1) + n + 1];
    const float4* __restrict__ xr = (const float4*)(g_x16 + (size_t)r * NS * DD); // 32 float4/row
    const float2* __restrict__ pr = g_pair + (size_t)r * EE;

    float acc[8] = {0,0,0,0,0,0,0,0};
    float wsum = 0.f;
    int i = beg;
    for (; i + 8 <= end; i += 8) {
        float2 p[8];
        float4 v[8];
#pragma unroll
        for (int j = 0; j < 8; j++) p[j] = __ldg(pr + i + j);
#pragma unroll
        for (int j = 0; j < 8; j++)
            v[j] = __ldg(xr + (size_t)__float_as_int(p[j].y)*32 + lane);
#pragma unroll
        for (int j = 0; j < 8; j++) { fma8(acc, p[j].x, v[j]); wsum += p[j].x; }
    }
    for (; i < end; i++) {
        float2 p = __ldg(pr + i);
        float4 v = __ldg(xr + (size_t)__float_as_int(p.y)*32 + lane);
        fma8(acc, p.x, v);
        wsum += p.x;
    }
    float inv = 1.f / fmaxf(wsum, 1e-9f);
    float4 hv;
    *(__half2*)&hv.x = __floats2half2_rn(acc[0]*inv, acc[1]*inv);
    *(__half2*)&hv.y = __floats2half2_rn(acc[2]*inv, acc[3]*inv);
    *(__half2*)&hv.z = __floats2half2_rn(acc[4]*inv, acc[5]*inv);
    *(__half2*)&hv.w = __floats2half2_rn(acc[6]*inv, acc[7]*inv);
    *(float4*)(g_H16 + (size_t)n * RD + r * DD + lane * 8) = hv;
}

// Candidate mask + relation-sum (R6 verbatim). One block per node, 256 thr.
__global__ void __launch_bounds__(256) k_mask(const int* __restrict__ cand,
                                              float* __restrict__ out) {
    __shared__ float buf[RD];
    __shared__ float s_sq[KK];
    int n = blockIdx.x;
    int t = threadIdx.x;
    int lane = t & 31;

    const uint2* __restrict__ Hh = (const uint2*)g_H16;   // 8B = 4 halves; RD/4 per row
    uint2 hr = __ldg(&Hh[(size_t)n * (RD/4) + t]);
    float2 h01 = __half22float2(*(__half2*)&hr.x);
    float2 h23 = __half22float2(*(__half2*)&hr.y);
    float4 h4 = make_float4(h01.x, h01.y, h23.x, h23.y);

    if (t < KK) s_sq[t] = 0.f;
    __syncthreads();

    float4 df[KK];
#pragma unroll
    for (int k = 0; k < KK; k++) {
        int c = __ldg(&cand[n*KK + k]);
        uint2 cr = __ldg(&Hh[(size_t)c * (RD/4) + t]);
        float2 f01 = __half22float2(*(__half2*)&cr.x);
        float2 f23 = __half22float2(*(__half2*)&cr.y);
        float4 d4;
        d4.x = h4.x - f01.x; d4.y = h4.y - f01.y;
        d4.z = h4.z - f23.x; d4.w = h4.w - f23.y;
        df[k] = d4;
        float p = d4.x*d4.x + d4.y*d4.y + d4.z*d4.z + d4.w*d4.w;
#pragma unroll
        for (int o = 16; o; o >>= 1) p += __shfl_down_sync(0xffffffffu, p, o);
        if (lane == 0) atomicAdd(&s_sq[k], p);
    }
    __syncthreads();

    float lg[KK];
    float mx = -1e30f;
#pragma unroll
    for (int k = 0; k < KK; k++) { lg[k] = -sqrtf(s_sq[k]); mx = fmaxf(mx, lg[k]); }
    float den = 0.f;
    float ek[KK];
#pragma unroll
    for (int k = 0; k < KK; k++) { ek[k] = expf(lg[k] - mx); den += ek[k]; }
    float invden = 1.f / den;

    float4 acc = make_float4(0.f, 0.f, 0.f, 0.f);
#pragma unroll
    for (int k = 0; k < KK; k++) {
        float a = ek[k] * invden;
        acc.x += a * df[k].x * df[k].x;
        acc.y += a * df[k].y * df[k].y;
        acc.z += a * df[k].z * df[k].z;
        acc.w += a * df[k].w * df[k].w;
    }
    float4 mv;
    mv.x = h4.x * expf(-acc.x);
    mv.y = h4.y * expf(-acc.y);
    mv.z = h4.z * expf(-acc.z);
    mv.w = h4.w * expf(-acc.w);
    ((float4*)buf)[t] = mv;
    __syncthreads();

    out[(size_t)n * DD + t] = buf[t] + buf[DD + t] + buf[2*DD + t] + buf[3*DD + t];
}

// ---------------------------------------------------------------------------
extern "C" void kernel_launch(void* const* d_in, const int* in_sizes, int n_in,
                              void* d_out, int out_size) {
    const float* x    = (const float*)d_in[0];   // [R, NS, D]
    const float* d    = (const float*)d_in[1];   // [R, NS]
    const float* d1   = (const float*)d_in[2];   // [R, NS]
    const float* d2   = (const float*)d_in[3];   // [R, NS]
    const int*   src  = (const int*)d_in[4];     // [R, E]
    const int*   dst  = (const int*)d_in[5];     // [R, E]
    const int*   cand = (const int*)d_in[6];     // [NV, K]
    const int*   spl  = (const int*)d_in[7];     // scalar splitvulid
    float* out = (float*)d_out;                  // [NV, D]

    k_conv_hist<<<(RR*EE + 255)/256, 256>>>(x, dst);          // launch 1
    k_scan<<<RR, 1024>>>();                                   // launch 2 (zeroes g_cnt)
    k_scatter2<<<(RR*EE + 255)/256, 256>>>(d, d1, d2, src, dst, spl); // launch 3
    k_aggregate<<<NV, 128>>>();                               // launch 4 <- profiled
    k_mask<<<NV, 256>>>(cand, out);                           // launch 5
}

// round 13
// speedup vs baseline: 1.7046x; 1.6185x over previous
#include <cuda_runtime.h>
#include <cuda_fp16.h>

// Problem constants (fixed shapes from reference setup_inputs)
#define RR 4          // relations
#define NS 20000      // N_SRC
#define NV 20000      // N_VUL (= N)
#define DD 256        // feature dim
#define EE 640000     // edges per relation
#define KK 16         // candidates per node
#define RD (RR*DD)    // 1024 halves per node across relations

// ---- scratch (static device globals; allocation-free per harness rules) ----
__device__ __half  g_x16[(size_t)RR*NS*DD];   // fp16 copy of x (41MB)
__device__ float2  g_pair[RR*EE];             // (w, src-as-int-bits) in CSR order (20MB)
__device__ int     g_cnt[RR*NV];              // in-degree histogram (zeroed by k_scan after use)
__device__ int     g_offs[RR*(NV+1)];         // CSR offsets
__device__ int     g_cursor[RR*NV];           // scatter cursors
__device__ __half  g_H16[(size_t)NV*RD];      // H fp16 [n][r][d] (41MB)

// ---------------------------------------------------------------------------
// Fused: degree histogram (1 edge/thread) + x fp32->fp16 convert.
// RR*NS*DD = 20.48M floats = 10.24M half2 = 4 * (RR*EE) half2: each thread
// converts 4 half2 at stride RR*EE (coalesced passes) + 1 histogram edge.
__global__ void k_conv_hist(const float* __restrict__ x,
                            const int*   __restrict__ dst_idx) {
    int idx = blockIdx.x * blockDim.x + threadIdx.x;
    if (idx >= RR*EE) return;
    const float2* __restrict__ x2 = (const float2*)x;
    __half2* __restrict__ o = (__half2*)g_x16;
#pragma unroll
    for (int j = 0; j < 4; j++) {
        int e = idx + j * (RR*EE);
        float2 v = __ldg(x2 + e);
        o[e] = __floats2half2_rn(v.x, v.y);
    }
    int r = idx / EE;
    atomicAdd(&g_cnt[r*NV + dst_idx[idx]], 1);
}

// Coalesced tiled exclusive scan. One block of 1024 per relation.
// Re-zeroes g_cnt after reading (first run relies on static zero-init).
__global__ void __launch_bounds__(1024) k_scan() {
    __shared__ int warpsums[32];
    int r    = blockIdx.x;
    int t    = threadIdx.x;
    int lane = t & 31;
    int w    = t >> 5;
    int carry = 0;
    const int NT = (NV + 1023) / 1024;   // 20 tiles
    for (int tile = 0; tile < NT; tile++) {
        int i = tile * 1024 + t;
        int v = (i < NV) ? g_cnt[r*NV + i] : 0;
        int s = v;
#pragma unroll
        for (int o = 1; o < 32; o <<= 1) {
            int u = __shfl_up_sync(0xffffffffu, s, o);
            if (lane >= o) s += u;
        }
        if (lane == 31) warpsums[w] = s;
        __syncthreads();
        if (w == 0) {
            int ws = warpsums[lane];
#pragma unroll
            for (int o = 1; o < 32; o <<= 1) {
                int u = __shfl_up_sync(0xffffffffu, ws, o);
                if (lane >= o) ws += u;
            }
            warpsums[lane] = ws;
        }
        __syncthreads();
        int excl = carry + ((w > 0) ? warpsums[w-1] : 0) + s - v;
        if (i < NV) {
            g_offs[r*(NV+1) + i] = excl;
            g_cursor[r*NV + i]   = excl;
            g_cnt[r*NV + i]      = 0;
        }
        carry += warpsums[31];
        __syncthreads();
    }
    if (t == 0) g_offs[r*(NV+1) + NV] = carry;
}

// Combined: softmax weight (max-subtraction dropped: logits bounded in [-2,2])
// + counting-sort scatter of paired (w, src) into CSR order.
__global__ void k_scatter2(const float* __restrict__ d,
                           const float* __restrict__ d1,
                           const float* __restrict__ d2,
                           const int*   __restrict__ src_idx,
                           const int*   __restrict__ dst_idx,
                           const int*   __restrict__ psplit) {
    int idx = blockIdx.x * blockDim.x + threadIdx.x;
    if (idx >= RR*EE) return;
    int r   = idx / EE;
    int src = src_idx[idx];
    int dst = dst_idx[idx];
    float dd = __ldg(&d[r*NS + src]);
    int   split = *psplit;
    float lg = (dst < split) ? (__ldg(&d1[r*NS + src]) / dd)
                             : (-__ldg(&d2[r*NS + src]) / dd);
    float w = expf(lg);
    int pos = atomicAdd(&g_cursor[r*NV + dst], 1);
    g_pair[r*EE + pos] = make_float2(w, __int_as_float(src));
}

// fp16 octet FMA into fp32 accumulators
__device__ __forceinline__ void fma8(float* acc, float w, float4 raw) {
    float2 f0 = __half22float2(*(__half2*)&raw.x);
    float2 f1 = __half22float2(*(__half2*)&raw.y);
    float2 f2 = __half22float2(*(__half2*)&raw.z);
    float2 f3 = __half22float2(*(__half2*)&raw.w);
    acc[0] += w*f0.x; acc[1] += w*f0.y; acc[2] += w*f1.x; acc[3] += w*f1.y;
    acc[4] += w*f2.x; acc[5] += w*f2.y; acc[6] += w*f3.x; acc[7] += w*f3.y;
}

// Gather-aggregate (R6/541us winner, VERBATIM — measured 89.8us, issue 61.5%).
__global__ void __launch_bounds__(128) k_aggregate() {
    int n    = blockIdx.x;
    int r    = threadIdx.x >> 5;
    int lane = threadIdx.x & 31;
    int beg = g_offs[r*(NV+1) + n];
    int end = g_offs[r*(NV+1) + n + 1];
    const float4* __restrict__ xr = (const float4*)(g_x16 + (size_t)r * NS * DD); // 32 float4/row
    const float2* __restrict__ pr = g_pair + (size_t)r * EE;

    float acc[8] = {0,0,0,0,0,0,0,0};
    float wsum = 0.f;
    int i = beg;
    for (; i + 8 <= end; i += 8) {
        float2 p[8];
        float4 v[8];
#pragma unroll
        for (int j = 0; j < 8; j++) p[j] = __ldg(pr + i + j);
#pragma unroll
        for (int j = 0; j < 8; j++)
            v[j] = __ldg(xr + (size_t)__float_as_int(p[j].y)*32 + lane);
#pragma unroll
        for (int j = 0; j < 8; j++) { fma8(acc, p[j].x, v[j]); wsum += p[j].x; }
    }
    for (; i < end; i++) {
        float2 p = __ldg(pr + i);
        float4 v = __ldg(xr + (size_t)__float_as_int(p.y)*32 + lane);
        fma8(acc, p.x, v);
        wsum += p.x;
    }
    float inv = 1.f / fmaxf(wsum, 1e-9f);
    float4 hv;
    *(__half2*)&hv.x = __floats2half2_rn(acc[0]*inv, acc[1]*inv);
    *(__half2*)&hv.y = __floats2half2_rn(acc[2]*inv, acc[3]*inv);
    *(__half2*)&hv.z = __floats2half2_rn(acc[4]*inv, acc[5]*inv);
    *(__half2*)&hv.w = __floats2half2_rn(acc[6]*inv, acc[7]*inv);
    *(float4*)(g_H16 + (size_t)n * RD + r * DD + lane * 8) = hv;
}

// Candidate mask + relation-sum, warp-per-candidate rewrite.
// 8 warps x 2 candidates: warp diffs its candidate rows against the own row
// in half2, stages diffs in smem (32KB), ONE warp-reduction per candidate
// (no smem atomics, no per-thread df/lg/ek arrays -> ~40 regs, no spills).
__global__ void __launch_bounds__(256) k_mask(const int* __restrict__ cand,
                                              float* __restrict__ out) {
    __shared__ __half s_df[KK][RD];   // 32KB candidate diffs
    __shared__ float  s_sq[KK];
    __shared__ float  buf[RD];        // 4KB
    int n = blockIdx.x;
    int t = threadIdx.x;
    int w = t >> 5, lane = t & 31;

    const float4* __restrict__ Hrow = (const float4*)(g_H16 + (size_t)n * RD); // 128 float4
    // own row, warp-distributed: lane holds float4 j*32+lane (8 halves each)
    float4 h[4];
#pragma unroll
    for (int j = 0; j < 4; j++) h[j] = __ldg(Hrow + j*32 + lane);

#pragma unroll
    for (int c = 0; c < 2; c++) {
        int k = w*2 + c;
        int cidx = __ldg(&cand[n*KK + k]);
        const float4* __restrict__ Crow = (const float4*)(g_H16 + (size_t)cidx * RD);
        float sq = 0.f;
#pragma unroll
        for (int j = 0; j < 4; j++) {
            float4 cv = __ldg(Crow + j*32 + lane);
            __half2 dd[4];
#pragma unroll
            for (int q = 0; q < 4; q++) {
                dd[q] = __hsub2(((const __half2*)&h[j])[q], ((const __half2*)&cv)[q]);
                float2 f = __half22float2(dd[q]);
                sq += f.x*f.x + f.y*f.y;
            }
            ((float4*)(&s_df[k][0]))[j*32 + lane] = *(float4*)dd;
        }
#pragma unroll
        for (int o = 16; o; o >>= 1) sq += __shfl_down_sync(0xffffffffu, sq, o);
        if (lane == 0) s_sq[k] = sq;
    }
    __syncthreads();

    // per-thread softmax over k (recomputed from smem; no register arrays)
    float mx = -1e30f;
#pragma unroll
    for (int k = 0; k < KK; k++) mx = fmaxf(mx, -sqrtf(s_sq[k]));
    float den = 0.f;
#pragma unroll
    for (int k = 0; k < KK; k++) den += expf(-sqrtf(s_sq[k]) - mx);
    float invden = 1.f / den;

    // accumulate attention-weighted squared diffs for this thread's 4 elements
    float4 acc = make_float4(0.f, 0.f, 0.f, 0.f);
#pragma unroll
    for (int k = 0; k < KK; k++) {
        float a = expf(-sqrtf(s_sq[k]) - mx) * invden;
        uint2 dr = *(const uint2*)&s_df[k][t*4];
        float2 f01 = __half22float2(*(__half2*)&dr.x);
        float2 f23 = __half22float2(*(__half2*)&dr.y);
        acc.x += a*f01.x*f01.x; acc.y += a*f01.y*f01.y;
        acc.z += a*f23.x*f23.x; acc.w += a*f23.y*f23.y;
    }

    // own elements for thread t (L1-hot reload, 8B)
    uint2 hr = *(const uint2*)(g_H16 + (size_t)n * RD + t*4);
    float2 h01 = __half22float2(*(__half2*)&hr.x);
    float2 h23 = __half22float2(*(__half2*)&hr.y);
    float4 mv;
    mv.x = h01.x * expf(-acc.x);
    mv.y = h01.y * expf(-acc.y);
    mv.z = h23.x * expf(-acc.z);
    mv.w = h23.y * expf(-acc.w);
    ((float4*)buf)[t] = mv;
    __syncthreads();

    // sum over relations: out[n][t] = sum_r buf[r*DD + t]
    out[(size_t)n * DD + t] = buf[t] + buf[DD + t] + buf[2*DD + t] + buf[3*DD + t];
}

// ---------------------------------------------------------------------------
extern "C" void kernel_launch(void* const* d_in, const int* in_sizes, int n_in,
                              void* d_out, int out_size) {
    const float* x    = (const float*)d_in[0];   // [R, NS, D]
    const float* d    = (const float*)d_in[1];   // [R, NS]
    const float* d1   = (const float*)d_in[2];   // [R, NS]
    const float* d2   = (const float*)d_in[3];   // [R, NS]
    const int*   src  = (const int*)d_in[4];     // [R, E]
    const int*   dst  = (const int*)d_in[5];     // [R, E]
    const int*   cand = (const int*)d_in[6];     // [NV, K]
    const int*   spl  = (const int*)d_in[7];     // scalar splitvulid
    float* out = (float*)d_out;                  // [NV, D]

    k_conv_hist<<<(RR*EE + 255)/256, 256>>>(x, dst);
    k_scan<<<RR, 1024>>>();
    k_scatter2<<<(RR*EE + 255)/256, 256>>>(d, d1, d2, src, dst, spl);
    k_aggregate<<<NV, 128>>>();
    k_mask<<<NV, 256>>>(cand, out);
}